// round 3
// baseline (speedup 1.0000x reference)
#include <cuda_runtime.h>
#include <math.h>

#define BSZ 4
#define SEQ 2048
#define DMODEL 512
#define NH 8
#define HDIM 64
#define KW1 64
#define KW2 64
#define MROWS (BSZ * SEQ)   // 8192

// ---------------- scratch (device globals; allocation-free) ----------------
__device__ float g_q[(size_t)BSZ * NH * SEQ * HDIM];   // [B,H,L,HD]
__device__ float g_k[(size_t)BSZ * NH * SEQ * HDIM];
__device__ float g_v[(size_t)BSZ * NH * SEQ * HDIM];
__device__ float g_u[(size_t)BSZ * SEQ * DMODEL];      // [B,L,D]
__device__ float g_g[(size_t)BSZ * SEQ * DMODEL];      // silu(attn)*u, [B,L,D]

// ---------------- SGEMM: C[M,N] = A[M,K] @ B[N,K]^T + bias ----------------
// MODE 0: A=x, B = concat(w_qkv[1536,K], w_u[512,K]); epilogue scatters
//         q,k,v -> [B,H,L,HD] and u -> [B,L,D].
// MODE 1: A=g_g (device global), B=w_out; epilogue writes C + bias.
template <int MODE>
__global__ void __launch_bounds__(256)
sgemm_kernel(const float* __restrict__ A,
             const float* __restrict__ B1,
             const float* __restrict__ B2,
             const float* __restrict__ bias1,
             const float* __restrict__ bias2,
             float* __restrict__ C,
             int N, int K)
{
    __shared__ float As[8][128];
    __shared__ float Bs[8][128];

    const int tid = threadIdx.x;
    const int m0 = blockIdx.y * 128;
    const int n0 = blockIdx.x * 128;

    const float* Aptr = (MODE == 1) ? g_g : A;

    const int lr = tid >> 1;          // 0..127 row within tile
    const int lc = (tid & 1) << 2;    // 0 or 4 (float4 column)

    const float* arow = Aptr + (size_t)(m0 + lr) * K + lc;
    const int gn = n0 + lr;
    const float* brow;
    if (MODE == 0 && gn >= 1536)
        brow = B2 + (size_t)(gn - 1536) * K + lc;
    else
        brow = B1 + (size_t)gn * K + lc;

    const int ty = tid >> 4;          // 0..15
    const int tx = tid & 15;          // 0..15

    float acc[8][8];
#pragma unroll
    for (int i = 0; i < 8; i++)
#pragma unroll
        for (int j = 0; j < 8; j++) acc[i][j] = 0.f;

    for (int k0 = 0; k0 < K; k0 += 8) {
        float4 av = *(const float4*)(arow + k0);
        float4 bv = *(const float4*)(brow + k0);
        __syncthreads();
        As[lc + 0][lr] = av.x; As[lc + 1][lr] = av.y;
        As[lc + 2][lr] = av.z; As[lc + 3][lr] = av.w;
        Bs[lc + 0][lr] = bv.x; Bs[lc + 1][lr] = bv.y;
        Bs[lc + 2][lr] = bv.z; Bs[lc + 3][lr] = bv.w;
        __syncthreads();
#pragma unroll
        for (int kk = 0; kk < 8; kk++) {
            float a[8], b[8];
            *(float4*)(a)     = *(const float4*)(&As[kk][ty * 8]);
            *(float4*)(a + 4) = *(const float4*)(&As[kk][ty * 8 + 4]);
            *(float4*)(b)     = *(const float4*)(&Bs[kk][tx * 8]);
            *(float4*)(b + 4) = *(const float4*)(&Bs[kk][tx * 8 + 4]);
#pragma unroll
            for (int i = 0; i < 8; i++)
#pragma unroll
                for (int j = 0; j < 8; j++) acc[i][j] += a[i] * b[j];
        }
    }

    // ---------------- epilogue ----------------
#pragma unroll
    for (int ii = 0; ii < 8; ii++) {
        const int m = m0 + ty * 8 + ii;
        if (MODE == 0) {
            const int b = m >> 11;        // m / SEQ
            const int l = m & 2047;       // m % SEQ
#pragma unroll
            for (int jj = 0; jj < 8; jj++) {
                const int n = n0 + tx * 8 + jj;
                float v = acc[ii][jj];
                if (n < 1536) {
                    v += bias1[n];
                    const int s = n >> 9;             // 0=q,1=k,2=v
                    const int h = (n >> 6) & 7;
                    const int d = n & 63;
                    float* dst = (s == 0) ? g_q : (s == 1) ? g_k : g_v;
                    dst[((((size_t)b * NH + h) * SEQ) + l) * HDIM + d] = v;
                } else {
                    v += bias2[n - 1536];
                    g_u[(size_t)m * DMODEL + (n - 1536)] = v;
                }
            }
        } else {
#pragma unroll
            for (int jj = 0; jj < 8; jj++) {
                const int n = n0 + tx * 8 + jj;
                C[(size_t)m * N + n] = acc[ii][jj] + bias1[n];
            }
        }
    }
}

// ---------------- sparse semi-local attention + SiLU gate ----------------
// One warp per (b,h,i). Allowed keys for query i:
//   glob:  j in [0, g_hi],  g_hi = min(K2, L-i, i)
//   band:  j in [max(L-K1-i, g_hi+1), min(i, L-i)]   (dedup'd vs glob)
// n_keys <= 130.
__global__ void __launch_bounds__(256)
attn_kernel()
{
    const int warp = (blockIdx.x * blockDim.x + threadIdx.x) >> 5;
    const int lane = threadIdx.x & 31;
    const int i  = warp & (SEQ - 1);
    const int bh = warp >> 11;            // b*NH + h, 0..31

    const float* qrow = g_q + ((size_t)bh * SEQ + i) * HDIM;
    const float2 qv = *(const float2*)(qrow + (lane << 1));

    const int g_hi   = min(min(KW2, SEQ - i), i);
    const int band_lo = max(SEQ - KW1 - i, g_hi + 1);
    const int band_hi = min(i, SEQ - i);
    const int nb = max(0, band_hi - band_lo + 1);
    const int n_keys = g_hi + 1 + nb;

    const float* kbase = g_k + (size_t)bh * SEQ * HDIM;
    const float* vbase = g_v + (size_t)bh * SEQ * HDIM;
    const float scale = 0.125f;   // 1/sqrt(64)

    float sc[5];
#pragma unroll
    for (int s = 0; s < 5; s++) sc[s] = -INFINITY;

    // ---- QK^T (4 keys per butterfly round for ILP) ----
#pragma unroll
    for (int s = 0; s < 5; s++) {
        const int tbase = s * 32;
        if (tbase < n_keys) {
            float mysc = -INFINITY;
            for (int r0 = 0; r0 < 32 && tbase + r0 < n_keys; r0 += 4) {
                float p[4];
#pragma unroll
                for (int u = 0; u < 4; u++) {
                    const int t = tbase + r0 + u;
                    float pr = 0.f;
                    if (t < n_keys) {
                        const int j = (t <= g_hi) ? t : band_lo + (t - g_hi - 1);
                        const float2 kv2 =
                            *(const float2*)(kbase + (size_t)j * HDIM + (lane << 1));
                        pr = qv.x * kv2.x + qv.y * kv2.y;
                    }
                    p[u] = pr;
                }
#pragma unroll
                for (int off = 16; off; off >>= 1) {
                    p[0] += __shfl_xor_sync(0xffffffffu, p[0], off);
                    p[1] += __shfl_xor_sync(0xffffffffu, p[1], off);
                    p[2] += __shfl_xor_sync(0xffffffffu, p[2], off);
                    p[3] += __shfl_xor_sync(0xffffffffu, p[3], off);
                }
#pragma unroll
                for (int u = 0; u < 4; u++) {
                    if (tbase + r0 + u < n_keys && lane == r0 + u)
                        mysc = p[u] * scale;
                }
            }
            sc[s] = mysc;
        }
    }

    // ---- softmax over the (distributed) scores ----
    float m = sc[0];
#pragma unroll
    for (int s = 1; s < 5; s++) m = fmaxf(m, sc[s]);
#pragma unroll
    for (int off = 16; off; off >>= 1)
        m = fmaxf(m, __shfl_xor_sync(0xffffffffu, m, off));

    float pe[5];
    float lsum = 0.f;
#pragma unroll
    for (int s = 0; s < 5; s++) {
        pe[s] = __expf(sc[s] - m);        // sc=-inf -> 0
        lsum += pe[s];
    }
#pragma unroll
    for (int off = 16; off; off >>= 1)
        lsum += __shfl_xor_sync(0xffffffffu, lsum, off);
    const float inv_denom = 1.f / lsum;

    // ---- P @ V ----
    float o0 = 0.f, o1 = 0.f;
#pragma unroll
    for (int s = 0; s < 5; s++) {
        const int tbase = s * 32;
        if (tbase < n_keys) {
            const float myp = pe[s];
            const int tmax = min(32, n_keys - tbase);
            for (int r = 0; r < tmax; r++) {
                const float pt = __shfl_sync(0xffffffffu, myp, r);
                const int t = tbase + r;
                const int j = (t <= g_hi) ? t : band_lo + (t - g_hi - 1);
                const float2 vv =
                    *(const float2*)(vbase + (size_t)j * HDIM + (lane << 1));
                o0 += pt * vv.x;
                o1 += pt * vv.y;
            }
        }
    }
    o0 *= inv_denom;
    o1 *= inv_denom;

    // ---- SiLU gate fused: g = silu(o) * u ----
    const int b = bh >> 3;
    const int h = bh & 7;
    const size_t uidx =
        ((size_t)(b * SEQ + i)) * DMODEL + h * HDIM + (lane << 1);
    const float2 uu = *(const float2*)(g_u + uidx);
    float2 out;
    out.x = (o0 / (1.f + __expf(-o0))) * uu.x;
    out.y = (o1 / (1.f + __expf(-o1))) * uu.y;
    *(float2*)(g_g + uidx) = out;
}

// ---------------- launch ----------------
extern "C" void kernel_launch(void* const* d_in, const int* in_sizes, int n_in,
                              void* d_out, int out_size)
{
    const float* x     = (const float*)d_in[0];
    const float* w_qkv = (const float*)d_in[1];
    const float* b_qkv = (const float*)d_in[2];
    const float* w_u   = (const float*)d_in[3];
    const float* b_u   = (const float*)d_in[4];
    const float* w_out = (const float*)d_in[5];
    const float* b_out = (const float*)d_in[6];
    float* out = (float*)d_out;

    // Fused QKV+U projection: [8192,512] @ [2048,512]^T
    {
        dim3 grid(2048 / 128, MROWS / 128);
        sgemm_kernel<0><<<grid, 256>>>(x, w_qkv, w_u, b_qkv, b_u,
                                       nullptr, 2048, DMODEL);
    }

    // Sparse attention + SiLU*u gate: 65536 warps
    {
        const int warps = BSZ * NH * SEQ;          // 65536
        attn_kernel<<<warps / 8, 256>>>();
    }

    // Output projection: [8192,512] @ [512,512]^T
    {
        dim3 grid(DMODEL / 128, MROWS / 128);
        sgemm_kernel<1><<<grid, 256>>>(nullptr, w_out, nullptr, b_out,
                                       nullptr, out, DMODEL, DMODEL);
    }
}

// round 5
// speedup vs baseline: 2.0945x; 2.0945x over previous
#include <cuda_runtime.h>
#include <cuda_bf16.h>
#include <math.h>
#include <stdint.h>

#define BSZ 4
#define SEQ 2048
#define DMODEL 512
#define NH 8
#define HDIM 64
#define KW1 64
#define KW2 64
#define MROWS (BSZ * SEQ)   // 8192

// ---------------- scratch (device globals; allocation-free) ----------------
__device__ float g_q[(size_t)BSZ * NH * SEQ * HDIM];   // [B,H,L,HD]
__device__ float g_k[(size_t)BSZ * NH * SEQ * HDIM];
__device__ float g_v[(size_t)BSZ * NH * SEQ * HDIM];
__device__ float g_u[(size_t)MROWS * DMODEL];          // [B,L,D]
__device__ float g_g[(size_t)MROWS * DMODEL];          // silu(attn)*u

// split-bf16 operands (hi + lo, K-major rows of 512)
__device__ __nv_bfloat16 gXh[(size_t)MROWS * DMODEL];
__device__ __nv_bfloat16 gXl[(size_t)MROWS * DMODEL];
__device__ __nv_bfloat16 gWh[(size_t)2048 * DMODEL];   // [w_qkv ; w_u]
__device__ __nv_bfloat16 gWl[(size_t)2048 * DMODEL];
__device__ __nv_bfloat16 gOh[(size_t)DMODEL * DMODEL]; // w_out
__device__ __nv_bfloat16 gOl[(size_t)DMODEL * DMODEL];
__device__ __nv_bfloat16 gGh[(size_t)MROWS * DMODEL];  // gated activations
__device__ __nv_bfloat16 gGl[(size_t)MROWS * DMODEL];

// ======================= PTX helpers (sm_80+ only, no 'a' features) ========
__device__ __forceinline__ uint32_t smem_u32(const void* p) {
    uint32_t a;
    asm("{ .reg .u64 t; cvta.to.shared.u64 t, %1; cvt.u32.u64 %0, t; }"
        : "=r"(a) : "l"(p));
    return a;
}
#define CP_ASYNC16(dst, src) \
    asm volatile("cp.async.cg.shared.global [%0], [%1], 16;" :: "r"(dst), "l"(src) : "memory")
#define CP_COMMIT() asm volatile("cp.async.commit_group;" ::: "memory")
#define CP_WAIT(n) asm volatile("cp.async.wait_group %0;" :: "n"(n) : "memory")

__device__ __forceinline__ void ldsm4(uint32_t r[4], uint32_t addr) {
    asm volatile("ldmatrix.sync.aligned.m8n8.x4.shared.b16 {%0,%1,%2,%3}, [%4];"
                 : "=r"(r[0]), "=r"(r[1]), "=r"(r[2]), "=r"(r[3]) : "r"(addr));
}
__device__ __forceinline__ void mma16816(float c[4], const uint32_t a[4],
                                         const uint32_t b[2]) {
    asm volatile(
        "mma.sync.aligned.m16n8k16.row.col.f32.bf16.bf16.f32 "
        "{%0,%1,%2,%3},{%4,%5,%6,%7},{%8,%9},{%0,%1,%2,%3};"
        : "+f"(c[0]), "+f"(c[1]), "+f"(c[2]), "+f"(c[3])
        : "r"(a[0]), "r"(a[1]), "r"(a[2]), "r"(a[3]), "r"(b[0]), "r"(b[1]));
}

// ======================= split conversion =======================
__global__ void __launch_bounds__(256)
split_kernel(const float* __restrict__ src, __nv_bfloat16* __restrict__ hi,
             __nv_bfloat16* __restrict__ lo, int n)
{
    int i = blockIdx.x * blockDim.x + threadIdx.x;
    if (i < n) {
        float a = src[i];
        __nv_bfloat16 h = __float2bfloat16(a);
        hi[i] = h;
        lo[i] = __float2bfloat16(a - __bfloat162float(h));
    }
}

// ======================= HMMA split-bf16 GEMM =======================
// C[M,N] = (Ah+Al)[M,512] @ (Bh+Bl)[N,512]^T   (hh + hl + lh terms)
// Block tile 128x128, BK=32, 256 thr = 8 warps (2m x 4n), warp tile 64x32.
// smem tiles: 128 rows x 32 bf16, row stride 80B (conflict-free ldmatrix).
#define TSTRIDE 80
#define TILEB (128 * TSTRIDE)     // 10240
#define STAGEB (4 * TILEB)        // Ah, Al, Bh, Bl
#define GSMEM (2 * STAGEB)        // 81920

template <int MODE>
__global__ void __launch_bounds__(256, 1)
gemm_hmma(const __nv_bfloat16* __restrict__ Ah, const __nv_bfloat16* __restrict__ Al,
          const __nv_bfloat16* __restrict__ Bh, const __nv_bfloat16* __restrict__ Bl,
          const float* __restrict__ bias1, const float* __restrict__ bias2,
          float* __restrict__ C, int Ntot)
{
    extern __shared__ char smem[];
    const uint32_t sb = smem_u32(smem);
    const int tid = threadIdx.x, lane = tid & 31, wid = tid >> 5;
    const int wm = wid & 1, wn = wid >> 1;        // 2 x 4 warp grid
    const int m0 = blockIdx.y * 128, n0 = blockIdx.x * 128;

    // loader: 4 tiles x 64 threads; thread covers 8 (row,chunk) slots
    const int lt = tid >> 6;          // tile id
    const int lidx = tid & 63;
    const __nv_bfloat16* lbase;
    {
        const __nv_bfloat16* s0 = Ah + (size_t)m0 * 512;
        const __nv_bfloat16* s1 = Al + (size_t)m0 * 512;
        const __nv_bfloat16* s2 = Bh + (size_t)n0 * 512;
        const __nv_bfloat16* s3 = Bl + (size_t)n0 * 512;
        lbase = (lt == 0) ? s0 : (lt == 1) ? s1 : (lt == 2) ? s2 : s3;
    }
    const int lrow0 = lidx >> 2;      // base row (stepped by 16 per it)
    const int lch = lidx & 3;         // 16B chunk 0..3
    const uint32_t ldst0 = sb + lt * TILEB + lrow0 * TSTRIDE + lch * 16;
    const __nv_bfloat16* lsrc0 = lbase + (size_t)lrow0 * 512 + lch * 8;

    auto load_stage = [&](int s) {
        const uint32_t d0 = ldst0 + (s & 1) * STAGEB;
        const __nv_bfloat16* g0 = lsrc0 + s * 32;
#pragma unroll
        for (int it = 0; it < 8; it++)
            CP_ASYNC16(d0 + it * (16 * TSTRIDE), g0 + (size_t)it * (16 * 512));
    };

    float acc[4][4][4];
#pragma unroll
    for (int a = 0; a < 4; a++)
#pragma unroll
        for (int b = 0; b < 4; b++)
#pragma unroll
            for (int c = 0; c < 4; c++) acc[a][b][c] = 0.f;

    // frag addressing (per-lane constants)
    const int arow = wm * 64 + (lane & 15);
    const int asub = lane >> 4;                              // k-chunk sub
    const int brow = wn * 32 + (lane & 7) + ((lane >> 4) << 3);
    const int bsub = (lane >> 3) & 1;

    load_stage(0); CP_COMMIT();

#pragma unroll 1
    for (int s = 0; s < 16; s++) {
        if (s < 15) { load_stage(s + 1); CP_COMMIT(); CP_WAIT(1); }
        else CP_WAIT(0);
        __syncthreads();
        const uint32_t st = sb + (s & 1) * STAGEB;
#pragma unroll
        for (int kp = 0; kp < 2; kp++) {
            uint32_t ah[4][4], al[4][4], bh[4][2], bl[4][2];
            const int ach = kp * 2 + asub;
            const int bch = kp * 2 + bsub;
#pragma unroll
            for (int im = 0; im < 4; im++) {
                const uint32_t off = (arow + im * 16) * TSTRIDE + ach * 16;
                ldsm4(ah[im], st + 0 * TILEB + off);
                ldsm4(al[im], st + 1 * TILEB + off);
            }
#pragma unroll
            for (int jn = 0; jn < 2; jn++) {
                const uint32_t off = (brow + jn * 16) * TSTRIDE + bch * 16;
                uint32_t r[4];
                ldsm4(r, st + 2 * TILEB + off);
                bh[jn * 2][0] = r[0]; bh[jn * 2][1] = r[1];
                bh[jn * 2 + 1][0] = r[2]; bh[jn * 2 + 1][1] = r[3];
                ldsm4(r, st + 3 * TILEB + off);
                bl[jn * 2][0] = r[0]; bl[jn * 2][1] = r[1];
                bl[jn * 2 + 1][0] = r[2]; bl[jn * 2 + 1][1] = r[3];
            }
#pragma unroll
            for (int im = 0; im < 4; im++)
#pragma unroll
                for (int in = 0; in < 4; in++) {
                    mma16816(acc[im][in], ah[im], bh[in]);
                    mma16816(acc[im][in], ah[im], bl[in]);
                    mma16816(acc[im][in], al[im], bh[in]);
                }
        }
        __syncthreads();
    }

    // ---------------- epilogue (from registers) ----------------
    const int r0 = m0 + wm * 64 + (lane >> 2);
    const int cb = n0 + wn * 32;
#pragma unroll
    for (int im = 0; im < 4; im++) {
#pragma unroll
        for (int in = 0; in < 4; in++) {
            const int col = cb + in * 8 + (lane & 3) * 2;
            if (MODE == 0) {
                const int nb = cb + in * 8;       // frag-uniform segment
                const bool isu = (nb >= 1536);
                float bx, by;
                float* dst = nullptr;
                int h = 0;
                if (!isu) {
                    const int sg = nb >> 9;
                    h = (nb >> 6) & 7;
                    dst = (sg == 0) ? g_q : (sg == 1) ? g_k : g_v;
                    const float2 bv = *(const float2*)&bias1[col];
                    bx = bv.x; by = bv.y;
                } else {
                    const float2 bv = *(const float2*)&bias2[col - 1536];
                    bx = bv.x; by = bv.y;
                }
#pragma unroll
                for (int hf = 0; hf < 2; hf++) {
                    const int row = r0 + im * 16 + hf * 8;
                    float2 v;
                    v.x = acc[im][in][hf * 2] + bx;
                    v.y = acc[im][in][hf * 2 + 1] + by;
                    if (!isu) {
                        const int bb = row >> 11, l = row & (SEQ - 1);
                        *(float2*)&dst[(((size_t)(bb * NH + h)) * SEQ + l) * HDIM +
                                       (col & 63)] = v;
                    } else {
                        *(float2*)&g_u[(size_t)row * DMODEL + (col - 1536)] = v;
                    }
                }
            } else {
                const float2 bv = *(const float2*)&bias1[col];
#pragma unroll
                for (int hf = 0; hf < 2; hf++) {
                    const int row = r0 + im * 16 + hf * 8;
                    float2 v;
                    v.x = acc[im][in][hf * 2] + bv.x;
                    v.y = acc[im][in][hf * 2 + 1] + bv.y;
                    *(float2*)&C[(size_t)row * Ntot + col] = v;
                }
            }
        }
    }
}

// ---------------- sparse semi-local attention + SiLU gate ----------------
// One warp per (b,h,i). QK: 4 keys/round, 8 lanes per key (full 128B lines),
// 3 shfl per round. Scores/probs staged in smem; PV uses LDS broadcast.
__global__ void __launch_bounds__(256)
attn_kernel()
{
    __shared__ float sp[8][176];
    const int wid = threadIdx.x >> 5, lane = threadIdx.x & 31;
    const int gw = blockIdx.x * 8 + wid;
    const int i  = gw & (SEQ - 1);
    const int bh = gw >> 11;            // b*NH + h

    const int g_hi    = min(min(KW2, SEQ - i), i);
    const int band_lo = max(SEQ - KW1 - i, g_hi + 1);
    const int band_hi = min(i, SEQ - i);
    const int nb = max(0, band_hi - band_lo + 1);
    const int n_keys = g_hi + 1 + nb;

    const float* kbase = g_k + (size_t)bh * SEQ * HDIM;
    const float* vbase = g_v + (size_t)bh * SEQ * HDIM;
    const float* qrow  = g_q + ((size_t)bh * SEQ + i) * HDIM;

    const int c = lane & 7;             // 16B chunk within row (c and c+8)
    const int g = lane >> 3;            // key sub-index within 4-key group
    const float4 qa = *(const float4*)(qrow + c * 4);
    const float4 qb = *(const float4*)(qrow + 32 + c * 4);

    // ---- QK^T ----
    const int ngroups = (n_keys + 3) >> 2;
    for (int it = 0; it < ngroups; it++) {
        const int t = it * 4 + g;
        const bool valid = t < n_keys;
        int j = (t <= g_hi) ? t : band_lo + (t - g_hi - 1);
        j = valid ? j : 0;
        const float* krow = kbase + (size_t)j * HDIM;
        const float4 ka = *(const float4*)(krow + c * 4);
        const float4 kb = *(const float4*)(krow + 32 + c * 4);
        float p = qa.x * ka.x + qa.y * ka.y + qa.z * ka.z + qa.w * ka.w
                + qb.x * kb.x + qb.y * kb.y + qb.z * kb.z + qb.w * kb.w;
        p += __shfl_xor_sync(0xffffffffu, p, 4);
        p += __shfl_xor_sync(0xffffffffu, p, 2);
        p += __shfl_xor_sync(0xffffffffu, p, 1);
        if (valid && c == 0) sp[wid][t] = p * 0.125f;
    }
    __syncwarp();

    // ---- softmax (scores distributed: lane owns t = lane + 32s) ----
    float sc[5];
    float m = -INFINITY;
#pragma unroll
    for (int s = 0; s < 5; s++) {
        const int t = lane + 32 * s;
        sc[s] = (t < n_keys) ? sp[wid][t] : -INFINITY;
        m = fmaxf(m, sc[s]);
    }
#pragma unroll
    for (int off = 16; off; off >>= 1)
        m = fmaxf(m, __shfl_xor_sync(0xffffffffu, m, off));

    float lsum = 0.f;
#pragma unroll
    for (int s = 0; s < 5; s++) {
        const int t = lane + 32 * s;
        if (t < n_keys) {
            const float e = __expf(sc[s] - m);
            lsum += e;
            sp[wid][t] = e;
        }
    }
#pragma unroll
    for (int off = 16; off; off >>= 1)
        lsum += __shfl_xor_sync(0xffffffffu, lsum, off);
    const float inv_denom = 1.f / lsum;
    __syncwarp();

    // ---- P @ V (p via LDS broadcast; warp covers full V row) ----
    float o0 = 0.f, o1 = 0.f;
    const float* vlane = vbase + 2 * lane;
#pragma unroll 2
    for (int t = 0; t < n_keys; t++) {
        const float p = sp[wid][t];
        const int j = (t <= g_hi) ? t : band_lo + (t - g_hi - 1);
        const float2 vv = *(const float2*)(vlane + (size_t)j * HDIM);
        o0 += p * vv.x;
        o1 += p * vv.y;
    }
    o0 *= inv_denom;
    o1 *= inv_denom;

    // ---- SiLU gate fused: g = silu(o) * u ----
    const int b = bh >> 3;
    const int h = bh & 7;
    const size_t uidx =
        ((size_t)(b * SEQ + i)) * DMODEL + h * HDIM + 2 * lane;
    const float2 uu = *(const float2*)(g_u + uidx);
    float2 out;
    out.x = (o0 / (1.f + __expf(-o0))) * uu.x;
    out.y = (o1 / (1.f + __expf(-o1))) * uu.y;
    *(float2*)(g_g + uidx) = out;
}

// ---------------- launch ----------------
extern "C" void kernel_launch(void* const* d_in, const int* in_sizes, int n_in,
                              void* d_out, int out_size)
{
    const float* x     = (const float*)d_in[0];
    const float* w_qkv = (const float*)d_in[1];
    const float* b_qkv = (const float*)d_in[2];
    const float* w_u   = (const float*)d_in[3];
    const float* b_u   = (const float*)d_in[4];
    const float* w_out = (const float*)d_in[5];
    const float* b_out = (const float*)d_in[6];
    float* out = (float*)d_out;

    void *pXh, *pXl, *pWh, *pWl, *pOh, *pOl, *pGh, *pGl, *pG;
    cudaGetSymbolAddress(&pXh, gXh); cudaGetSymbolAddress(&pXl, gXl);
    cudaGetSymbolAddress(&pWh, gWh); cudaGetSymbolAddress(&pWl, gWl);
    cudaGetSymbolAddress(&pOh, gOh); cudaGetSymbolAddress(&pOl, gOl);
    cudaGetSymbolAddress(&pGh, gGh); cudaGetSymbolAddress(&pGl, gGl);
    cudaGetSymbolAddress(&pG,  g_g);

    cudaFuncSetAttribute(gemm_hmma<0>, cudaFuncAttributeMaxDynamicSharedMemorySize, GSMEM);
    cudaFuncSetAttribute(gemm_hmma<1>, cudaFuncAttributeMaxDynamicSharedMemorySize, GSMEM);

    // split conversions
    {
        int n = MROWS * DMODEL;
        split_kernel<<<n / 256, 256>>>(x, (__nv_bfloat16*)pXh, (__nv_bfloat16*)pXl, n);
        int nq = 1536 * DMODEL;
        split_kernel<<<(nq + 255) / 256, 256>>>(w_qkv, (__nv_bfloat16*)pWh,
                                                (__nv_bfloat16*)pWl, nq);
        int nu = 512 * DMODEL;
        split_kernel<<<(nu + 255) / 256, 256>>>(
            w_u, (__nv_bfloat16*)pWh + (size_t)1536 * DMODEL,
            (__nv_bfloat16*)pWl + (size_t)1536 * DMODEL, nu);
        split_kernel<<<(nu + 255) / 256, 256>>>(w_out, (__nv_bfloat16*)pOh,
                                                (__nv_bfloat16*)pOl, nu);
    }

    // fused QKV+U projection: [8192,512] @ [2048,512]^T on HMMA
    {
        dim3 grid(2048 / 128, MROWS / 128);
        gemm_hmma<0><<<grid, 256, GSMEM>>>(
            (const __nv_bfloat16*)pXh, (const __nv_bfloat16*)pXl,
            (const __nv_bfloat16*)pWh, (const __nv_bfloat16*)pWl,
            b_qkv, b_u, nullptr, 2048);
    }

    // sparse attention + SiLU*u gate
    {
        const int warps = BSZ * NH * SEQ;
        attn_kernel<<<warps / 8, 256>>>();
    }

    // split gated activations, then output projection
    {
        int n = MROWS * DMODEL;
        split_kernel<<<n / 256, 256>>>((const float*)pG, (__nv_bfloat16*)pGh,
                                       (__nv_bfloat16*)pGl, n);
        dim3 grid(DMODEL / 128, MROWS / 128);
        gemm_hmma<1><<<grid, 256, GSMEM>>>(
            (const __nv_bfloat16*)pGh, (const __nv_bfloat16*)pGl,
            (const __nv_bfloat16*)pOh, (const __nv_bfloat16*)pOl,
            b_out, nullptr, out, DMODEL);
    }
}

// round 6
// speedup vs baseline: 3.0404x; 1.4516x over previous
#include <cuda_runtime.h>
#include <cuda_bf16.h>
#include <math.h>
#include <stdint.h>

#define BSZ 4
#define SEQ 2048
#define DMODEL 512
#define NH 8
#define HDIM 64
#define KW1 64
#define KW2 64
#define MROWS (BSZ * SEQ)   // 8192

// ---------------- scratch (device globals; allocation-free) ----------------
__device__ float g_q[(size_t)BSZ * NH * SEQ * HDIM];   // [B,H,L,HD]
__device__ float g_k[(size_t)BSZ * NH * SEQ * HDIM];
__device__ float g_v[(size_t)BSZ * NH * SEQ * HDIM];
__device__ float g_u[(size_t)MROWS * DMODEL];          // [B,L,D]

// split-bf16 operands (hi + lo, K-major rows of 512)
__device__ __nv_bfloat16 gXh[(size_t)MROWS * DMODEL];
__device__ __nv_bfloat16 gXl[(size_t)MROWS * DMODEL];
__device__ __nv_bfloat16 gWh[(size_t)2048 * DMODEL];   // [w_qkv ; w_u]
__device__ __nv_bfloat16 gWl[(size_t)2048 * DMODEL];
__device__ __nv_bfloat16 gOh[(size_t)DMODEL * DMODEL]; // w_out
__device__ __nv_bfloat16 gOl[(size_t)DMODEL * DMODEL];
__device__ __nv_bfloat16 gGh[(size_t)MROWS * DMODEL];  // gated activations
__device__ __nv_bfloat16 gGl[(size_t)MROWS * DMODEL];

// ======================= PTX helpers (sm_80+ only) =========================
__device__ __forceinline__ uint32_t smem_u32(const void* p) {
    uint32_t a;
    asm("{ .reg .u64 t; cvta.to.shared.u64 t, %1; cvt.u32.u64 %0, t; }"
        : "=r"(a) : "l"(p));
    return a;
}
#define CP_ASYNC16(dst, src) \
    asm volatile("cp.async.cg.shared.global [%0], [%1], 16;" :: "r"(dst), "l"(src) : "memory")
#define CP_COMMIT() asm volatile("cp.async.commit_group;" ::: "memory")
#define CP_WAIT(n) asm volatile("cp.async.wait_group %0;" :: "n"(n) : "memory")

__device__ __forceinline__ void ldsm4(uint32_t r[4], uint32_t addr) {
    asm volatile("ldmatrix.sync.aligned.m8n8.x4.shared.b16 {%0,%1,%2,%3}, [%4];"
                 : "=r"(r[0]), "=r"(r[1]), "=r"(r[2]), "=r"(r[3]) : "r"(addr));
}
__device__ __forceinline__ void mma16816(float c[4], const uint32_t a[4],
                                         const uint32_t b[2]) {
    asm volatile(
        "mma.sync.aligned.m16n8k16.row.col.f32.bf16.bf16.f32 "
        "{%0,%1,%2,%3},{%4,%5,%6,%7},{%8,%9},{%0,%1,%2,%3};"
        : "+f"(c[0]), "+f"(c[1]), "+f"(c[2]), "+f"(c[3])
        : "r"(a[0]), "r"(a[1]), "r"(a[2]), "r"(a[3]), "r"(b[0]), "r"(b[1]));
}

// ======================= split conversion =======================
__global__ void __launch_bounds__(256)
split_kernel(const float* __restrict__ src, __nv_bfloat16* __restrict__ hi,
             __nv_bfloat16* __restrict__ lo, int n)
{
    int i = blockIdx.x * blockDim.x + threadIdx.x;
    if (i < n) {
        float a = src[i];
        __nv_bfloat16 h = __float2bfloat16(a);
        hi[i] = h;
        lo[i] = __float2bfloat16(a - __bfloat162float(h));
    }
}

// ======================= HMMA split-bf16 GEMM =======================
// C[M,N] = (Ah+Al)[M,512] @ (Bh+Bl)[N,512]^T   (hh + lh + hl terms)
// Block tile 128x128, BK=32, 256 thr = 8 warps (2m x 4n), warp tile 64x32.
// smem: 128 rows x 64B, XOR swizzle chunk^((row>>1)&3) -> conflict-free,
// 32KB/stage, 2 stages = 64KB -> 2 CTAs/SM.
#define TILEB 8192                // 128 * 64
#define STAGEB (4 * TILEB)        // Ah, Al, Bh, Bl
#define GSMEM (2 * STAGEB)        // 65536

template <int MODE>
__global__ void __launch_bounds__(256, 2)
gemm_hmma(const __nv_bfloat16* __restrict__ Ah, const __nv_bfloat16* __restrict__ Al,
          const __nv_bfloat16* __restrict__ Bh, const __nv_bfloat16* __restrict__ Bl,
          const float* __restrict__ bias1, const float* __restrict__ bias2,
          float* __restrict__ C, int Ntot)
{
    extern __shared__ char smem[];
    const uint32_t sb = smem_u32(smem);
    const int tid = threadIdx.x, lane = tid & 31, wid = tid >> 5;
    const int wm = wid & 1, wn = wid >> 1;        // 2 x 4 warp grid
    const int m0 = blockIdx.y * 128, n0 = blockIdx.x * 128;

    // loader: 4 op-tiles x 64 threads; thread covers 8 (row,chunk) slots
    const int lt = tid >> 6;
    const int lidx = tid & 63;
    const __nv_bfloat16* lbase;
    {
        const __nv_bfloat16* s0 = Ah + (size_t)m0 * 512;
        const __nv_bfloat16* s1 = Al + (size_t)m0 * 512;
        const __nv_bfloat16* s2 = Bh + (size_t)n0 * 512;
        const __nv_bfloat16* s3 = Bl + (size_t)n0 * 512;
        lbase = (lt == 0) ? s0 : (lt == 1) ? s1 : (lt == 2) ? s2 : s3;
    }
    const int lrow0 = lidx >> 2;          // 0..15 (step 16 per it)
    const int lch = lidx & 3;
    const int lsc = lch ^ ((lrow0 >> 1) & 3);   // swizzled 16B slot (it-invariant)
    const uint32_t ldst0 = sb + lt * TILEB + lrow0 * 64 + lsc * 16;
    const __nv_bfloat16* lsrc0 = lbase + (size_t)lrow0 * 512 + lch * 8;

    auto load_stage = [&](int s) {
        const uint32_t d0 = ldst0 + (s & 1) * STAGEB;
        const __nv_bfloat16* g0 = lsrc0 + s * 32;
#pragma unroll
        for (int it = 0; it < 8; it++)
            CP_ASYNC16(d0 + it * 1024, g0 + (size_t)it * (16 * 512));
    };

    float acc[4][4][4];
#pragma unroll
    for (int a = 0; a < 4; a++)
#pragma unroll
        for (int b = 0; b < 4; b++)
#pragma unroll
            for (int c = 0; c < 4; c++) acc[a][b][c] = 0.f;

    // frag addressing (lane constants; im*16 rows keep (row>>1)&3 invariant)
    const int arow = wm * 64 + (lane & 15);
    const int asub = lane >> 4;
    const int aswz = (arow >> 1) & 3;
    const uint32_t abase = arow * 64;
    const int brow = wn * 32 + (lane & 7) + ((lane >> 4) << 3);
    const int bsub = (lane >> 3) & 1;
    const int bswz = (brow >> 1) & 3;
    const uint32_t bbase = brow * 64;

    load_stage(0); CP_COMMIT();

#pragma unroll 1
    for (int s = 0; s < 16; s++) {
        if (s < 15) { load_stage(s + 1); CP_COMMIT(); CP_WAIT(1); }
        else CP_WAIT(0);
        __syncthreads();
        const uint32_t st = sb + (s & 1) * STAGEB;
#pragma unroll
        for (int kp = 0; kp < 2; kp++) {
            const uint32_t aoff = abase + (((kp * 2 + asub) ^ aswz) * 16);
            const uint32_t boff = bbase + (((kp * 2 + bsub) ^ bswz) * 16);
            uint32_t ah[4][4], al[4][4], bb[4][2];
#pragma unroll
            for (int im = 0; im < 4; im++)
                ldsm4(ah[im], st + 0 * TILEB + aoff + im * 1024);
#pragma unroll
            for (int jn = 0; jn < 2; jn++) {
                uint32_t r[4];
                ldsm4(r, st + 2 * TILEB + boff + jn * 1024);
                bb[jn * 2][0] = r[0]; bb[jn * 2][1] = r[1];
                bb[jn * 2 + 1][0] = r[2]; bb[jn * 2 + 1][1] = r[3];
            }
#pragma unroll
            for (int im = 0; im < 4; im++)
#pragma unroll
                for (int in = 0; in < 4; in++) mma16816(acc[im][in], ah[im], bb[in]);
#pragma unroll
            for (int im = 0; im < 4; im++)
                ldsm4(al[im], st + 1 * TILEB + aoff + im * 1024);
#pragma unroll
            for (int im = 0; im < 4; im++)
#pragma unroll
                for (int in = 0; in < 4; in++) mma16816(acc[im][in], al[im], bb[in]);
#pragma unroll
            for (int jn = 0; jn < 2; jn++) {
                uint32_t r[4];
                ldsm4(r, st + 3 * TILEB + boff + jn * 1024);
                bb[jn * 2][0] = r[0]; bb[jn * 2][1] = r[1];
                bb[jn * 2 + 1][0] = r[2]; bb[jn * 2 + 1][1] = r[3];
            }
#pragma unroll
            for (int im = 0; im < 4; im++)
#pragma unroll
                for (int in = 0; in < 4; in++) mma16816(acc[im][in], ah[im], bb[in]);
        }
        __syncthreads();
    }

    // ---------------- epilogue (from registers) ----------------
    const int r0 = m0 + wm * 64 + (lane >> 2);
    const int cb = n0 + wn * 32;
#pragma unroll
    for (int im = 0; im < 4; im++) {
#pragma unroll
        for (int in = 0; in < 4; in++) {
            const int col = cb + in * 8 + (lane & 3) * 2;
            if (MODE == 0) {
                const int nb = cb + in * 8;       // frag-uniform segment
                const bool isu = (nb >= 1536);
                float bx, by;
                float* dst = nullptr;
                int h = 0;
                if (!isu) {
                    const int sg = nb >> 9;
                    h = (nb >> 6) & 7;
                    dst = (sg == 0) ? g_q : (sg == 1) ? g_k : g_v;
                    const float2 bv = *(const float2*)&bias1[col];
                    bx = bv.x; by = bv.y;
                } else {
                    const float2 bv = *(const float2*)&bias2[col - 1536];
                    bx = bv.x; by = bv.y;
                }
#pragma unroll
                for (int hf = 0; hf < 2; hf++) {
                    const int row = r0 + im * 16 + hf * 8;
                    float2 v;
                    v.x = acc[im][in][hf * 2] + bx;
                    v.y = acc[im][in][hf * 2 + 1] + by;
                    if (!isu) {
                        const int bb2 = row >> 11, l = row & (SEQ - 1);
                        *(float2*)&dst[(((size_t)(bb2 * NH + h)) * SEQ + l) * HDIM +
                                       (col & 63)] = v;
                    } else {
                        *(float2*)&g_u[(size_t)row * DMODEL + (col - 1536)] = v;
                    }
                }
            } else {
                const float2 bv = *(const float2*)&bias1[col];
#pragma unroll
                for (int hf = 0; hf < 2; hf++) {
                    const int row = r0 + im * 16 + hf * 8;
                    float2 v;
                    v.x = acc[im][in][hf * 2] + bv.x;
                    v.y = acc[im][in][hf * 2 + 1] + bv.y;
                    *(float2*)&C[(size_t)row * Ntot + col] = v;
                }
            }
        }
    }
}

// ---------------- sparse semi-local attention + SiLU gate ----------------
// One warp per 4 CONSECUTIVE queries (same bh): K/V rows loaded once per
// 4 queries (4x traffic cut). Key union = prefix [0,p_hi] + band [blo,bhi],
// per-query validity by exact mask formula. Epilogue writes split-bf16
// gGh/gGl directly (g-split fused).
#define NTMAX 160
__global__ void __launch_bounds__(256)
attn_kernel()
{
    __shared__ float sp[8][4][NTMAX];
    const int wid = threadIdx.x >> 5, lane = threadIdx.x & 31;
    const int gw = blockIdx.x * 8 + wid;          // 0..16383
    const int qb = (gw << 2) & (SEQ - 1);
    const int bh = (gw << 2) >> 11;

    // union key-range for queries qb..qb+3
    int p_hi = 0, bhi = 0;
#pragma unroll
    for (int qq = 0; qq < 4; qq++) {
        const int ii = qb + qq;
        p_hi = max(p_hi, min(min(KW2, SEQ - ii), ii));
        bhi  = max(bhi, min(ii, SEQ - ii));
    }
    const int blo = max(SEQ - KW1 - (qb + 3), p_hi + 1);
    const int n1 = p_hi + 1;
    const int n2 = max(0, bhi - blo + 1);
    const int nt = n1 + n2;

    const float* kbase = g_k + (size_t)bh * SEQ * HDIM;
    const float* vbase = g_v + (size_t)bh * SEQ * HDIM;

    const int c = lane & 7;             // 16B chunk within row (c and c+8)
    const int g = lane >> 3;            // key sub-index within 4-key group

    float4 qa[4], qc[4];
#pragma unroll
    for (int qq = 0; qq < 4; qq++) {
        const float* qrow = g_q + ((size_t)bh * SEQ + qb + qq) * HDIM;
        qa[qq] = *(const float4*)(qrow + c * 4);
        qc[qq] = *(const float4*)(qrow + 32 + c * 4);
    }

    // ---- QK^T over union slots ----
    const int ngroups = (nt + 3) >> 2;
    for (int it = 0; it < ngroups; it++) {
        const int t = it * 4 + g;
        const bool valid = t < nt;
        int j = (t < n1) ? t : blo + (t - n1);
        j = valid ? j : 0;
        const float* krow = kbase + (size_t)j * HDIM;
        const float4 ka = *(const float4*)(krow + c * 4);
        const float4 kc = *(const float4*)(krow + 32 + c * 4);
        float p[4];
#pragma unroll
        for (int qq = 0; qq < 4; qq++) {
            p[qq] = qa[qq].x * ka.x + qa[qq].y * ka.y + qa[qq].z * ka.z + qa[qq].w * ka.w
                  + qc[qq].x * kc.x + qc[qq].y * kc.y + qc[qq].z * kc.z + qc[qq].w * kc.w;
        }
#pragma unroll
        for (int off = 4; off; off >>= 1) {
            p[0] += __shfl_xor_sync(0xffffffffu, p[0], off);
            p[1] += __shfl_xor_sync(0xffffffffu, p[1], off);
            p[2] += __shfl_xor_sync(0xffffffffu, p[2], off);
            p[3] += __shfl_xor_sync(0xffffffffu, p[3], off);
        }
        if (valid && c == 0) {
#pragma unroll
            for (int qq = 0; qq < 4; qq++) sp[wid][qq][t] = p[qq] * 0.125f;
        }
    }
    __syncwarp();

    // ---- per-query masked softmax (probs written back to sp) ----
    float inv_denom[4];
#pragma unroll
    for (int qq = 0; qq < 4; qq++) {
        const int ii = qb + qq;
        float scv[5];
        float m = -INFINITY;
#pragma unroll
        for (int s = 0; s < 5; s++) {
            const int t = lane + 32 * s;
            float v = -INFINITY;
            if (t < nt) {
                const int j = (t < n1) ? t : blo + (t - n1);
                const bool ok = (j <= ii) &&
                    (((ii + j >= SEQ - KW1) && (ii + j <= SEQ)) ||
                     ((j <= KW2) && (j <= SEQ - ii)));
                v = ok ? sp[wid][qq][t] : -INFINITY;
            }
            scv[s] = v;
            m = fmaxf(m, v);
        }
#pragma unroll
        for (int off = 16; off; off >>= 1)
            m = fmaxf(m, __shfl_xor_sync(0xffffffffu, m, off));
        float lsum = 0.f;
#pragma unroll
        for (int s = 0; s < 5; s++) {
            const int t = lane + 32 * s;
            if (t < nt) {
                const float e = __expf(scv[s] - m);
                lsum += e;
                sp[wid][qq][t] = e;
            }
        }
#pragma unroll
        for (int off = 16; off; off >>= 1)
            lsum += __shfl_xor_sync(0xffffffffu, lsum, off);
        inv_denom[qq] = 1.f / lsum;
    }
    __syncwarp();

    // ---- P @ V (V row loaded once per 4 queries; p via LDS broadcast) ----
    float o0[4] = {0.f, 0.f, 0.f, 0.f}, o1[4] = {0.f, 0.f, 0.f, 0.f};
    const float* vlane = vbase + 2 * lane;
#pragma unroll 2
    for (int t = 0; t < nt; t++) {
        const int j = (t < n1) ? t : blo + (t - n1);
        const float2 vv = *(const float2*)(vlane + (size_t)j * HDIM);
#pragma unroll
        for (int qq = 0; qq < 4; qq++) {
            const float p = sp[wid][qq][t];
            o0[qq] += p * vv.x;
            o1[qq] += p * vv.y;
        }
    }

    // ---- SiLU gate + fused bf16 split write ----
    const int b = bh >> 3;
    const int h = bh & 7;
#pragma unroll
    for (int qq = 0; qq < 4; qq++) {
        const float a0 = o0[qq] * inv_denom[qq];
        const float a1 = o1[qq] * inv_denom[qq];
        const size_t uidx =
            ((size_t)(b * SEQ + qb + qq)) * DMODEL + h * HDIM + 2 * lane;
        const float2 uu = *(const float2*)(g_u + uidx);
        const float gx = (a0 / (1.f + __expf(-a0))) * uu.x;
        const float gy = (a1 / (1.f + __expf(-a1))) * uu.y;
        __nv_bfloat162 hv, lv;
        hv.x = __float2bfloat16(gx);
        hv.y = __float2bfloat16(gy);
        lv.x = __float2bfloat16(gx - __bfloat162float(hv.x));
        lv.y = __float2bfloat16(gy - __bfloat162float(hv.y));
        *(__nv_bfloat162*)&gGh[uidx] = hv;
        *(__nv_bfloat162*)&gGl[uidx] = lv;
    }
}

// ---------------- launch ----------------
extern "C" void kernel_launch(void* const* d_in, const int* in_sizes, int n_in,
                              void* d_out, int out_size)
{
    const float* x     = (const float*)d_in[0];
    const float* w_qkv = (const float*)d_in[1];
    const float* b_qkv = (const float*)d_in[2];
    const float* w_u   = (const float*)d_in[3];
    const float* b_u   = (const float*)d_in[4];
    const float* w_out = (const float*)d_in[5];
    const float* b_out = (const float*)d_in[6];
    float* out = (float*)d_out;

    void *pXh, *pXl, *pWh, *pWl, *pOh, *pOl, *pGh, *pGl;
    cudaGetSymbolAddress(&pXh, gXh); cudaGetSymbolAddress(&pXl, gXl);
    cudaGetSymbolAddress(&pWh, gWh); cudaGetSymbolAddress(&pWl, gWl);
    cudaGetSymbolAddress(&pOh, gOh); cudaGetSymbolAddress(&pOl, gOl);
    cudaGetSymbolAddress(&pGh, gGh); cudaGetSymbolAddress(&pGl, gGl);

    cudaFuncSetAttribute(gemm_hmma<0>, cudaFuncAttributeMaxDynamicSharedMemorySize, GSMEM);
    cudaFuncSetAttribute(gemm_hmma<1>, cudaFuncAttributeMaxDynamicSharedMemorySize, GSMEM);

    // split conversions (inputs + weights)
    {
        int n = MROWS * DMODEL;
        split_kernel<<<n / 256, 256>>>(x, (__nv_bfloat16*)pXh, (__nv_bfloat16*)pXl, n);
        int nq = 1536 * DMODEL;
        split_kernel<<<(nq + 255) / 256, 256>>>(w_qkv, (__nv_bfloat16*)pWh,
                                                (__nv_bfloat16*)pWl, nq);
        int nu = 512 * DMODEL;
        split_kernel<<<(nu + 255) / 256, 256>>>(
            w_u, (__nv_bfloat16*)pWh + (size_t)1536 * DMODEL,
            (__nv_bfloat16*)pWl + (size_t)1536 * DMODEL, nu);
        split_kernel<<<(nu + 255) / 256, 256>>>(w_out, (__nv_bfloat16*)pOh,
                                                (__nv_bfloat16*)pOl, nu);
    }

    // fused QKV+U projection: [8192,512] @ [2048,512]^T on HMMA
    {
        dim3 grid(2048 / 128, MROWS / 128);
        gemm_hmma<0><<<grid, 256, GSMEM>>>(
            (const __nv_bfloat16*)pXh, (const __nv_bfloat16*)pXl,
            (const __nv_bfloat16*)pWh, (const __nv_bfloat16*)pWl,
            b_qkv, b_u, nullptr, 2048);
    }

    // sparse attention + SiLU*u gate + fused g-split (4 queries/warp)
    {
        const int warps = BSZ * NH * SEQ / 4;      // 16384
        attn_kernel<<<warps / 8, 256>>>();
    }

    // output projection: [8192,512] @ [512,512]^T on HMMA
    {
        dim3 grid(DMODEL / 128, MROWS / 128);
        gemm_hmma<1><<<grid, 256, GSMEM>>>(
            (const __nv_bfloat16*)pGh, (const __nv_bfloat16*)pGl,
            (const __nv_bfloat16*)pOh, (const __nv_bfloat16*)pOl,
            b_out, nullptr, out, DMODEL);
    }
}